// round 12
// baseline (speedup 1.0000x reference)
#include <cuda_runtime.h>

// Problem constants (fixed by reference): B=2, H=16, S=2048, D=64
#define S    2048
#define D    64
#define C    64            // chunk length
#define NC   (S / C)       // 32 chunks per head
#define NBH  32            // B*H
#define LD   (D + 4)       // smem row stride (68 floats = 272B, 16B-aligned)
#define NEGV (-10000.0f)

// Scratch (device globals: allocation-free)
__device__ __align__(16) float g_kv  [NBH * NC * D * D];   // per-chunk Kn^T V
__device__ __align__(16) float g_mpre[NBH * NC * D * D];   // exclusive prefix of g_kv
__device__ __align__(16) float g_vs  [NBH * NC * D];       // per-chunk V column sums
__device__ __align__(16) float g_sufa[NBH * NC * D];       // suffix (chunks after c) of g_vs

#define FMA4x4(A, a0, a1, a2, a3, b)                                        \
    A[0][0] += (a0) * (b).x; A[0][1] += (a0) * (b).y;                       \
    A[0][2] += (a0) * (b).z; A[0][3] += (a0) * (b).w;                       \
    A[1][0] += (a1) * (b).x; A[1][1] += (a1) * (b).y;                       \
    A[1][2] += (a1) * (b).z; A[1][3] += (a1) * (b).w;                       \
    A[2][0] += (a2) * (b).x; A[2][1] += (a2) * (b).y;                       \
    A[2][2] += (a2) * (b).z; A[2][3] += (a2) * (b).w;                       \
    A[3][0] += (a3) * (b).x; A[3][1] += (a3) * (b).y;                       \
    A[3][2] += (a3) * (b).z; A[3][3] += (a3) * (b).w;

// ---------------------------------------------------------------------------
// Pass 1: per chunk, compute KV[d1][d2] = sum_i kn[i][d1]*v[i][d2]
//         and VS[d] = sum_i v[i][d].   kn = K row L1-normalized.
// ---------------------------------------------------------------------------
__global__ void __launch_bounds__(256) pass1_kernel(const float* __restrict__ K,
                                                    const float* __restrict__ V) {
    __shared__ __align__(16) float kn[C * LD];
    __shared__ __align__(16) float vv[C * LD];
    const int c   = blockIdx.x;
    const int bh  = blockIdx.y;
    const int tid = threadIdx.x;
    const int base = (bh * S + c * C) * D;

    #pragma unroll 4
    for (int idx = tid; idx < C * D; idx += 256) {
        const int r = idx >> 6, col = idx & 63;
        kn[r * LD + col] = K[base + idx];
        vv[r * LD + col] = V[base + idx];
    }
    __syncthreads();

    if (tid < C) {
        float s = 0.f;
        #pragma unroll 8
        for (int d = 0; d < D; d++) s += fabsf(kn[tid * LD + d]);
        const float inv = 1.0f / s;
        #pragma unroll 8
        for (int d = 0; d < D; d++) kn[tid * LD + d] *= inv;
    }
    __syncthreads();

    const int ti = tid >> 4, tj = tid & 15;
    const int d1 = ti * 4, d2 = tj * 4;
    float acc[4][4] = {};
    #pragma unroll 8
    for (int i = 0; i < C; i++) {
        const float a0 = kn[i * LD + d1 + 0];
        const float a1 = kn[i * LD + d1 + 1];
        const float a2 = kn[i * LD + d1 + 2];
        const float a3 = kn[i * LD + d1 + 3];
        const float4 b = *(const float4*)&vv[i * LD + d2];
        FMA4x4(acc, a0, a1, a2, a3, b)
    }

    float* kvo = g_kv + (bh * NC + c) * (D * D);
    #pragma unroll
    for (int r = 0; r < 4; r++) {
        *(float4*)&kvo[(d1 + r) * D + d2] =
            make_float4(acc[r][0], acc[r][1], acc[r][2], acc[r][3]);
    }

    if (tid < D) {
        float s = 0.f;
        #pragma unroll 8
        for (int i = 0; i < C; i++) s += vv[i * LD + tid];
        g_vs[(bh * NC + c) * D + tid] = s;
    }
}

// ---------------------------------------------------------------------------
// Scan: exclusive prefix of KV over chunks -> Mpre; suffix of VS -> SufAfter
// ---------------------------------------------------------------------------
__global__ void __launch_bounds__(256) scan_kernel() {
    const int bh  = blockIdx.x;
    const int tid = threadIdx.x;
    const float* kvb = g_kv   + bh * NC * (D * D);
    float*       mpb = g_mpre + bh * NC * (D * D);
    const int off = tid * 16;

    float4 r0 = make_float4(0, 0, 0, 0);
    float4 r1 = r0, r2 = r0, r3 = r0;
    for (int cc = 0; cc < NC; cc++) {
        const float4* src = (const float4*)(kvb + cc * (D * D) + off);
        const float4 s0 = src[0], s1 = src[1], s2 = src[2], s3 = src[3];
        float4* dst = (float4*)(mpb + cc * (D * D) + off);
        dst[0] = r0; dst[1] = r1; dst[2] = r2; dst[3] = r3;
        r0.x += s0.x; r0.y += s0.y; r0.z += s0.z; r0.w += s0.w;
        r1.x += s1.x; r1.y += s1.y; r1.z += s1.z; r1.w += s1.w;
        r2.x += s2.x; r2.y += s2.y; r2.z += s2.z; r2.w += s2.w;
        r3.x += s3.x; r3.y += s3.y; r3.z += s3.z; r3.w += s3.w;
    }

    if (tid < D) {
        float s = 0.f;
        for (int cc = NC - 1; cc >= 0; cc--) {
            g_sufa[(bh * NC + cc) * D + tid] = s;
            s += g_vs[(bh * NC + cc) * D + tid];
        }
    }
}

// ---------------------------------------------------------------------------
// Pass 2: out = 0.125*(Qn @ Mpre) + W @ V + NEG * SufAfter
//         W[i][j] = 0.125*dot(qn_i, kn_j) if j<=i else NEG
// smem: qn | bufB (Mpre -> V) | knT (K transposed, then normalized) | W | sufa
// ---------------------------------------------------------------------------
__global__ void __launch_bounds__(256) pass2_kernel(const float* __restrict__ Q,
                                                    const float* __restrict__ K,
                                                    const float* __restrict__ V,
                                                    float* __restrict__ O) {
    extern __shared__ __align__(16) float sm[];
    float* qn   = sm;
    float* bufB = sm + 1 * C * LD;
    float* knT  = sm + 2 * C * LD;
    float* W    = sm + 3 * C * LD;
    float* sufa = sm + 4 * C * LD;

    const int c   = blockIdx.x;
    const int bh  = blockIdx.y;
    const int tid = threadIdx.x;
    const int base = (bh * S + c * C) * D;
    const float* mpg = g_mpre + (bh * NC + c) * (D * D);

    #pragma unroll 4
    for (int idx = tid; idx < C * D; idx += 256) {
        const int r = idx >> 6, col = idx & 63;
        qn[r * LD + col]   = Q[base + idx];
        bufB[r * LD + col] = mpg[idx];       // Mpre, layout [dd][d]
    }
    if (tid < D) sufa[tid] = g_sufa[(bh * NC + c) * D + tid];
    __syncthreads();

    if (tid < C) {  // L1-normalize q rows
        float s = 0.f;
        #pragma unroll 8
        for (int d = 0; d < D; d++) s += fabsf(qn[tid * LD + d]);
        const float inv = 1.0f / s;
        #pragma unroll 8
        for (int d = 0; d < D; d++) qn[tid * LD + d] *= inv;
    }
    __syncthreads();

    const int ti = tid >> 4, tj = tid & 15;
    const int i0 = ti * 4, j0 = tj * 4;

    // Phase A: acc = qn @ Mpre
    float acc[4][4] = {};
    #pragma unroll 8
    for (int dd = 0; dd < D; dd++) {
        const float a0 = qn[(i0 + 0) * LD + dd];
        const float a1 = qn[(i0 + 1) * LD + dd];
        const float a2 = qn[(i0 + 2) * LD + dd];
        const float a3 = qn[(i0 + 3) * LD + dd];
        const float4 b = *(const float4*)&bufB[dd * LD + j0];
        FMA4x4(acc, a0, a1, a2, a3, b)
    }
    {
        const float4 sf = *(const float4*)&sufa[j0];
        #pragma unroll
        for (int r = 0; r < 4; r++) {
            acc[r][0] = acc[r][0] * 0.125f + NEGV * sf.x;
            acc[r][1] = acc[r][1] * 0.125f + NEGV * sf.y;
            acc[r][2] = acc[r][2] * 0.125f + NEGV * sf.z;
            acc[r][3] = acc[r][3] * 0.125f + NEGV * sf.w;
        }
    }
    __syncthreads();  // done reading Mpre from bufB

    // Load K (transposed -> knT[dd][j]) and V (row-major -> bufB)
    #pragma unroll 4
    for (int idx = tid; idx < C * D; idx += 256) {
        const int r = idx >> 6, col = idx & 63;
        knT[col * LD + r]  = K[base + idx];
        bufB[r * LD + col] = V[base + idx];
    }
    __syncthreads();

    if (tid < C) {  // L1-normalize k rows (= columns of knT): conflict-free
        float s = 0.f;
        #pragma unroll 8
        for (int dd = 0; dd < D; dd++) s += fabsf(knT[dd * LD + tid]);
        const float inv = 1.0f / s;
        #pragma unroll 8
        for (int dd = 0; dd < D; dd++) knT[dd * LD + tid] *= inv;
    }
    __syncthreads();

    // Phase B: w = qn @ kn^T   (b-operand is knT rows -> float4, conflict-free)
    float w[4][4] = {};
    #pragma unroll 8
    for (int dd = 0; dd < D; dd++) {
        const float a0 = qn[(i0 + 0) * LD + dd];
        const float a1 = qn[(i0 + 1) * LD + dd];
        const float a2 = qn[(i0 + 2) * LD + dd];
        const float a3 = qn[(i0 + 3) * LD + dd];
        const float4 b = *(const float4*)&knT[dd * LD + j0];
        FMA4x4(w, a0, a1, a2, a3, b)
    }
    #pragma unroll
    for (int r = 0; r < 4; r++) {
        #pragma unroll
        for (int cc = 0; cc < 4; cc++) {
            const int i = i0 + r, j = j0 + cc;
            W[i * LD + j] = (j <= i) ? w[r][cc] * 0.125f : NEGV;
        }
    }
    __syncthreads();

    // Phase C: acc += W @ V
    #pragma unroll 8
    for (int j = 0; j < C; j++) {
        const float a0 = W[(i0 + 0) * LD + j];
        const float a1 = W[(i0 + 1) * LD + j];
        const float a2 = W[(i0 + 2) * LD + j];
        const float a3 = W[(i0 + 3) * LD + j];
        const float4 b = *(const float4*)&bufB[j * LD + j0];
        FMA4x4(acc, a0, a1, a2, a3, b)
    }

    float* ob = O + base;
    #pragma unroll
    for (int r = 0; r < 4; r++) {
        *(float4*)&ob[(i0 + r) * D + j0] =
            make_float4(acc[r][0], acc[r][1], acc[r][2], acc[r][3]);
    }
}

// ---------------------------------------------------------------------------
extern "C" void kernel_launch(void* const* d_in, const int* in_sizes, int n_in,
                              void* d_out, int out_size) {
    const float* q = (const float*)d_in[0];
    const float* k = (const float*)d_in[1];
    const float* v = (const float*)d_in[2];
    // d_in[3] = causal mask, structurally known -> unused
    float* o = (float*)d_out;

    const int smem2 = (4 * C * LD + D) * (int)sizeof(float);  // 69,888 B
    cudaFuncSetAttribute(pass2_kernel,
                         cudaFuncAttributeMaxDynamicSharedMemorySize, smem2);

    dim3 grid(NC, NBH);
    pass1_kernel<<<grid, 256>>>(k, v);
    scan_kernel<<<NBH, 256>>>();
    pass2_kernel<<<grid, 256, smem2>>>(q, k, v, o);
    (void)in_sizes; (void)n_in; (void)out_size;
}

// round 13
// speedup vs baseline: 1.0053x; 1.0053x over previous
#include <cuda_runtime.h>

// Problem constants (fixed by reference): B=2, H=16, S=2048, D=64
#define S    2048
#define D    64
#define C    64            // chunk length
#define NC   (S / C)       // 32 chunks per head
#define NBH  32            // B*H
#define LD   (D + 4)       // smem row stride (68 floats = 272B, 16B-aligned)
#define NEGV (-10000.0f)

// Scratch (device globals: allocation-free)
__device__ __align__(16) float g_kv  [NBH * NC * D * D];   // per-chunk Kn^T V
__device__ __align__(16) float g_mpre[NBH * NC * D * D];   // exclusive prefix of g_kv
__device__ __align__(16) float g_vs  [NBH * NC * D];       // per-chunk V column sums
__device__ __align__(16) float g_sufa[NBH * NC * D];       // suffix (chunks after c) of g_vs

#define FMA4x4(A, a0, a1, a2, a3, b)                                        \
    A[0][0] += (a0) * (b).x; A[0][1] += (a0) * (b).y;                       \
    A[0][2] += (a0) * (b).z; A[0][3] += (a0) * (b).w;                       \
    A[1][0] += (a1) * (b).x; A[1][1] += (a1) * (b).y;                       \
    A[1][2] += (a1) * (b).z; A[1][3] += (a1) * (b).w;                       \
    A[2][0] += (a2) * (b).x; A[2][1] += (a2) * (b).y;                       \
    A[2][2] += (a2) * (b).z; A[2][3] += (a2) * (b).w;                       \
    A[3][0] += (a3) * (b).x; A[3][1] += (a3) * (b).y;                       \
    A[3][2] += (a3) * (b).z; A[3][3] += (a3) * (b).w;

// ---------------------------------------------------------------------------
// Pass 1: per chunk, compute KV[d1][d2] = sum_i kn[i][d1]*v[i][d2]
//         and VS[d] = sum_i v[i][d].   kn = K row L1-normalized.
// ---------------------------------------------------------------------------
__global__ void __launch_bounds__(256) pass1_kernel(const float* __restrict__ K,
                                                    const float* __restrict__ V) {
    __shared__ __align__(16) float kn[C * LD];
    __shared__ __align__(16) float vv[C * LD];
    const int c   = blockIdx.x;
    const int bh  = blockIdx.y;
    const int tid = threadIdx.x;
    const int base = (bh * S + c * C) * D;

    #pragma unroll 4
    for (int idx = tid; idx < C * D; idx += 256) {
        const int r = idx >> 6, col = idx & 63;
        kn[r * LD + col] = K[base + idx];
        vv[r * LD + col] = V[base + idx];
    }
    __syncthreads();

    if (tid < C) {
        float s = 0.f;
        #pragma unroll 8
        for (int d = 0; d < D; d++) s += fabsf(kn[tid * LD + d]);
        const float inv = 1.0f / s;
        #pragma unroll 8
        for (int d = 0; d < D; d++) kn[tid * LD + d] *= inv;
    }
    __syncthreads();

    const int ti = tid >> 4, tj = tid & 15;
    const int d1 = ti * 4, d2 = tj * 4;
    float acc[4][4] = {};
    #pragma unroll 8
    for (int i = 0; i < C; i++) {
        const float a0 = kn[i * LD + d1 + 0];
        const float a1 = kn[i * LD + d1 + 1];
        const float a2 = kn[i * LD + d1 + 2];
        const float a3 = kn[i * LD + d1 + 3];
        const float4 b = *(const float4*)&vv[i * LD + d2];
        FMA4x4(acc, a0, a1, a2, a3, b)
    }

    float* kvo = g_kv + (bh * NC + c) * (D * D);
    #pragma unroll
    for (int r = 0; r < 4; r++) {
        *(float4*)&kvo[(d1 + r) * D + d2] =
            make_float4(acc[r][0], acc[r][1], acc[r][2], acc[r][3]);
    }

    if (tid < D) {
        float s = 0.f;
        #pragma unroll 8
        for (int i = 0; i < C; i++) s += vv[i * LD + tid];
        g_vs[(bh * NC + c) * D + tid] = s;
    }
}

// ---------------------------------------------------------------------------
// Scan: exclusive prefix of KV over chunks -> Mpre; suffix of VS -> SufAfter
// ---------------------------------------------------------------------------
__global__ void __launch_bounds__(256) scan_kernel() {
    const int bh  = blockIdx.x;
    const int tid = threadIdx.x;
    const float* kvb = g_kv   + bh * NC * (D * D);
    float*       mpb = g_mpre + bh * NC * (D * D);
    const int off = tid * 16;

    float4 r0 = make_float4(0, 0, 0, 0);
    float4 r1 = r0, r2 = r0, r3 = r0;
    for (int cc = 0; cc < NC; cc++) {
        const float4* src = (const float4*)(kvb + cc * (D * D) + off);
        const float4 s0 = src[0], s1 = src[1], s2 = src[2], s3 = src[3];
        float4* dst = (float4*)(mpb + cc * (D * D) + off);
        dst[0] = r0; dst[1] = r1; dst[2] = r2; dst[3] = r3;
        r0.x += s0.x; r0.y += s0.y; r0.z += s0.z; r0.w += s0.w;
        r1.x += s1.x; r1.y += s1.y; r1.z += s1.z; r1.w += s1.w;
        r2.x += s2.x; r2.y += s2.y; r2.z += s2.z; r2.w += s2.w;
        r3.x += s3.x; r3.y += s3.y; r3.z += s3.z; r3.w += s3.w;
    }

    if (tid < D) {
        float s = 0.f;
        for (int cc = NC - 1; cc >= 0; cc--) {
            g_sufa[(bh * NC + cc) * D + tid] = s;
            s += g_vs[(bh * NC + cc) * D + tid];
        }
    }
}

// ---------------------------------------------------------------------------
// Pass 2: out = 0.125*(Qn @ Mpre) + W @ V + NEG * SufAfter
//         W[i][j] = 0.125*dot(qn_i, kn_j) if j<=i else NEG
// smem: qn | bufB (Mpre -> V) | knT (K transposed, then normalized) | W | sufa
// ---------------------------------------------------------------------------
__global__ void __launch_bounds__(256) pass2_kernel(const float* __restrict__ Q,
                                                    const float* __restrict__ K,
                                                    const float* __restrict__ V,
                                                    float* __restrict__ O) {
    extern __shared__ __align__(16) float sm[];
    float* qn   = sm;
    float* bufB = sm + 1 * C * LD;
    float* knT  = sm + 2 * C * LD;
    float* W    = sm + 3 * C * LD;
    float* sufa = sm + 4 * C * LD;

    const int c   = blockIdx.x;
    const int bh  = blockIdx.y;
    const int tid = threadIdx.x;
    const int base = (bh * S + c * C) * D;
    const float* mpg = g_mpre + (bh * NC + c) * (D * D);

    #pragma unroll 4
    for (int idx = tid; idx < C * D; idx += 256) {
        const int r = idx >> 6, col = idx & 63;
        qn[r * LD + col]   = Q[base + idx];
        bufB[r * LD + col] = mpg[idx];       // Mpre, layout [dd][d]
    }
    if (tid < D) sufa[tid] = g_sufa[(bh * NC + c) * D + tid];
    __syncthreads();

    if (tid < C) {  // L1-normalize q rows
        float s = 0.f;
        #pragma unroll 8
        for (int d = 0; d < D; d++) s += fabsf(qn[tid * LD + d]);
        const float inv = 1.0f / s;
        #pragma unroll 8
        for (int d = 0; d < D; d++) qn[tid * LD + d] *= inv;
    }
    __syncthreads();

    const int ti = tid >> 4, tj = tid & 15;
    const int i0 = ti * 4, j0 = tj * 4;

    // Phase A: acc = qn @ Mpre
    float acc[4][4] = {};
    #pragma unroll 8
    for (int dd = 0; dd < D; dd++) {
        const float a0 = qn[(i0 + 0) * LD + dd];
        const float a1 = qn[(i0 + 1) * LD + dd];
        const float a2 = qn[(i0 + 2) * LD + dd];
        const float a3 = qn[(i0 + 3) * LD + dd];
        const float4 b = *(const float4*)&bufB[dd * LD + j0];
        FMA4x4(acc, a0, a1, a2, a3, b)
    }
    {
        const float4 sf = *(const float4*)&sufa[j0];
        #pragma unroll
        for (int r = 0; r < 4; r++) {
            acc[r][0] = acc[r][0] * 0.125f + NEGV * sf.x;
            acc[r][1] = acc[r][1] * 0.125f + NEGV * sf.y;
            acc[r][2] = acc[r][2] * 0.125f + NEGV * sf.z;
            acc[r][3] = acc[r][3] * 0.125f + NEGV * sf.w;
        }
    }
    __syncthreads();  // done reading Mpre from bufB

    // Load K (transposed -> knT[dd][j]) and V (row-major -> bufB)
    #pragma unroll 4
    for (int idx = tid; idx < C * D; idx += 256) {
        const int r = idx >> 6, col = idx & 63;
        knT[col * LD + r]  = K[base + idx];
        bufB[r * LD + col] = V[base + idx];
    }
    __syncthreads();

    if (tid < C) {  // L1-normalize k rows (= columns of knT): conflict-free
        float s = 0.f;
        #pragma unroll 8
        for (int dd = 0; dd < D; dd++) s += fabsf(knT[dd * LD + tid]);
        const float inv = 1.0f / s;
        #pragma unroll 8
        for (int dd = 0; dd < D; dd++) knT[dd * LD + tid] *= inv;
    }
    __syncthreads();

    // Phase B: w = qn @ kn^T   (b-operand is knT rows -> float4, conflict-free)
    float w[4][4] = {};
    #pragma unroll 8
    for (int dd = 0; dd < D; dd++) {
        const float a0 = qn[(i0 + 0) * LD + dd];
        const float a1 = qn[(i0 + 1) * LD + dd];
        const float a2 = qn[(i0 + 2) * LD + dd];
        const float a3 = qn[(i0 + 3) * LD + dd];
        const float4 b = *(const float4*)&knT[dd * LD + j0];
        FMA4x4(w, a0, a1, a2, a3, b)
    }
    #pragma unroll
    for (int r = 0; r < 4; r++) {
        #pragma unroll
        for (int cc = 0; cc < 4; cc++) {
            const int i = i0 + r, j = j0 + cc;
            W[i * LD + j] = (j <= i) ? w[r][cc] * 0.125f : NEGV;
        }
    }
    __syncthreads();

    // Phase C: acc += W @ V
    #pragma unroll 8
    for (int j = 0; j < C; j++) {
        const float a0 = W[(i0 + 0) * LD + j];
        const float a1 = W[(i0 + 1) * LD + j];
        const float a2 = W[(i0 + 2) * LD + j];
        const float a3 = W[(i0 + 3) * LD + j];
        const float4 b = *(const float4*)&bufB[j * LD + j0];
        FMA4x4(acc, a0, a1, a2, a3, b)
    }

    float* ob = O + base;
    #pragma unroll
    for (int r = 0; r < 4; r++) {
        *(float4*)&ob[(i0 + r) * D + j0] =
            make_float4(acc[r][0], acc[r][1], acc[r][2], acc[r][3]);
    }
}

// ---------------------------------------------------------------------------
extern "C" void kernel_launch(void* const* d_in, const int* in_sizes, int n_in,
                              void* d_out, int out_size) {
    const float* q = (const float*)d_in[0];
    const float* k = (const float*)d_in[1];
    const float* v = (const float*)d_in[2];
    // d_in[3] = causal mask, structurally known -> unused
    float* o = (float*)d_out;

    const int smem2 = (4 * C * LD + D) * (int)sizeof(float);  // 69,888 B
    cudaFuncSetAttribute(pass2_kernel,
                         cudaFuncAttributeMaxDynamicSharedMemorySize, smem2);

    dim3 grid(NC, NBH);
    pass1_kernel<<<grid, 256>>>(k, v);
    scan_kernel<<<NBH, 256>>>();
    pass2_kernel<<<grid, 256, smem2>>>(q, k, v, o);
    (void)in_sizes; (void)n_in; (void)out_size;
}